// round 11
// baseline (speedup 1.0000x reference)
#include <cuda_runtime.h>
#include <cstdint>

// Depthwise conv1d, K=7, 'same' padding, softmax over taps — single kernel,
// NO smem tile: neighbor halos via 6 warp shuffles (distance 1), warp-edge
// lanes take one predicated LDG.128 each. Softmax by threads 0..6 only
// (hides under the main LDG); one barrier for the 7 shared weights.
// Per-thread hot path: 1 LDG.128 + 6 SHFL + 28 FFMA + 1 STG.128.

#define KSIZE 7
#define T_LEN 4096
#define THREADS 256
#define BLOCK_ELEMS (THREADS * 4)   // 1024 = quarter row
#define FULLMASK 0xFFFFFFFFu

__global__ __launch_bounds__(THREADS)
void lconv1d_shfl_kernel(const float* __restrict__ x,
                         const float* __restrict__ wraw,
                         float* __restrict__ out) {
    __shared__ float sw[KSIZE];

    const int row  = blockIdx.x >> 2;                    // b*C + c
    const int tloc = (blockIdx.x & 3) * BLOCK_ELEMS + threadIdx.x * 4;
    const size_t g = (size_t)row * T_LEN + tloc;
    const int lane = threadIdx.x & 31;

    // Main load: one float4 per thread (exactly one global touch per byte).
    const float4 b = *reinterpret_cast<const float4*>(x + g);

    // Warp-edge halo loads (predicated; rare lanes only). Row edges -> zeros.
    float4 aL = make_float4(0.f, 0.f, 0.f, 0.f);
    float4 cR = make_float4(0.f, 0.f, 0.f, 0.f);
    if (lane == 0 && tloc > 0)
        aL = *reinterpret_cast<const float4*>(x + g - 4);
    if (lane == 31 && tloc + 4 < T_LEN)
        cR = *reinterpret_cast<const float4*>(x + g + 4);

    // Softmax over this row's head taps (threads 0..6 only; __expf/MUFU).
    if (threadIdx.x < KSIZE) {
        const int h = row & 15;                          // C=1024 multiple of H=16
        float v[KSIZE];
        float m = -1e30f;
        #pragma unroll
        for (int k = 0; k < KSIZE; k++) {
            v[k] = __ldg(&wraw[h * KSIZE + k]);
            m = fmaxf(m, v[k]);
        }
        float sum = 0.f;
        #pragma unroll
        for (int k = 0; k < KSIZE; k++) sum += __expf(v[k] - m);
        sw[threadIdx.x] = __expf(v[threadIdx.x] - m) / sum;
    }

    // Neighbor halos via distance-1 shuffles (uniform, full mask).
    float a1 = __shfl_up_sync(FULLMASK, b.y, 1);   // x[t-3]
    float a2 = __shfl_up_sync(FULLMASK, b.z, 1);   // x[t-2]
    float a3 = __shfl_up_sync(FULLMASK, b.w, 1);   // x[t-1]
    float c1 = __shfl_down_sync(FULLMASK, b.x, 1); // x[t+4]
    float c2 = __shfl_down_sync(FULLMASK, b.y, 1); // x[t+5]
    float c3 = __shfl_down_sync(FULLMASK, b.z, 1); // x[t+6]
    if (lane == 0)  { a1 = aL.y; a2 = aL.z; a3 = aL.w; }
    if (lane == 31) { c1 = cR.x; c2 = cR.y; c3 = cR.z; }

    __syncthreads();
    const float w0 = sw[0], w1 = sw[1], w2 = sw[2], w3 = sw[3],
                w4 = sw[4], w5 = sw[5], w6 = sw[6];

    float4 r;
    r.x = w0*a1  + w1*a2  + w2*a3  + w3*b.x + w4*b.y + w5*b.z + w6*b.w;
    r.y = w0*a2  + w1*a3  + w2*b.x + w3*b.y + w4*b.z + w5*b.w + w6*c1;
    r.z = w0*a3  + w1*b.x + w2*b.y + w3*b.z + w4*b.w + w5*c1  + w6*c2;
    r.w = w0*b.x + w1*b.y + w2*b.z + w3*b.w + w4*c1  + w5*c2  + w6*c3;

    *reinterpret_cast<float4*>(out + g) = r;
}

extern "C" void kernel_launch(void* const* d_in, const int* in_sizes, int n_in,
                              void* d_out, int out_size) {
    const float* x = (const float*)d_in[0];
    const float* w = (const float*)d_in[1];
    float* out = (float*)d_out;

    const int rows = in_sizes[0] / T_LEN;              // B*C = 16384
    const int blocks = rows * (T_LEN / BLOCK_ELEMS);   // 65536

    lconv1d_shfl_kernel<<<blocks, THREADS>>>(x, w, out);
}

// round 12
// speedup vs baseline: 1.1012x; 1.1012x over previous
#include <cuda_runtime.h>
#include <cstdint>

// Depthwise conv1d, K=7, 'same' padding, softmax over taps — single fused kernel.
// x: (B, C, T) fp32; weight: (H, 1, 7); head for channel c is c % H (H=16).
// R2/R8 tile chassis: TILE=2048, 8KB smem, MLP=2, register-reused middle chunk.
// Fixes vs R8: (1) wraw loads issued BEFORE tile LDGs so their latency overlaps;
// (2) sw padded to 8 -> two LDS.128 instead of seven LDS.32;
// (3) __ldcs/__stcs streaming hints (data touched exactly once).

#define KSIZE 7
#define TILE 2048
#define HALF (TILE / 2)
#define THREADS 256
#define SHIFT 4   // s[SHIFT + i] = x[t0 + i]; halo lives at s[1..3]
#define T_LEN 4096

__global__ __launch_bounds__(THREADS)
void lconv1d_fused_kernel(const float* __restrict__ x,
                          const float* __restrict__ wraw,
                          float* __restrict__ out) {
    __shared__ float s[SHIFT + TILE + 3];
    __shared__ __align__(16) float sw[8];

    const int row = blockIdx.y;               // b*C + c
    const int t0  = blockIdx.x * TILE;
    const size_t base = (size_t)row * T_LEN + t0;
    const int tid = threadIdx.x;
    const int p0 = tid * 4;
    const int p1 = p0 + HALF;

    // (1) Weight loads first (warp 0 lanes 0..6 only) — latency overlaps tile LDGs.
    float v[KSIZE];
    if (tid < KSIZE) {
        const int h = row & 15;               // C=1024 multiple of H=16
        #pragma unroll
        for (int k = 0; k < KSIZE; k++)
            v[k] = __ldg(&wraw[h * KSIZE + k]);
    }

    // Two independent main-tile loads per thread (MLP=2), streaming hint.
    const float4 v0 = __ldcs(reinterpret_cast<const float4*>(x + base + p0));
    const float4 v1 = __ldcs(reinterpret_cast<const float4*>(x + base + p1));

    // Halos (3 left, 3 right) with zero padding at row boundaries.
    float hl = 0.f, hr = 0.f;
    if (tid < 3) {
        if (t0 > 0)            hl = x[base - 3 + tid];
        if (t0 + TILE < T_LEN) hr = x[base + TILE + tid];
    }

    // Softmax math (MUFU) while tile LDGs are in flight.
    if (tid < KSIZE) {
        float m = -1e30f;
        #pragma unroll
        for (int k = 0; k < KSIZE; k++) m = fmaxf(m, v[k]);
        float sum = 0.f;
        #pragma unroll
        for (int k = 0; k < KSIZE; k++) sum += __expf(v[k] - m);
        sw[tid] = __expf(v[tid] - m) / sum;
        if (tid == 0) sw[7] = 0.f;
    }

    // Tile stores (dependent on LDGs), aligned STS.128.
    *reinterpret_cast<float4*>(&s[SHIFT + p0]) = v0;
    *reinterpret_cast<float4*>(&s[SHIFT + p1]) = v1;
    if (tid < 3) {
        s[1 + tid] = hl;
        s[SHIFT + TILE + tid] = hr;
    }

    __syncthreads();

    // (2) Weights via two LDS.128 (broadcast, conflict-free).
    const float4 wa = *reinterpret_cast<const float4*>(&sw[0]);
    const float4 wb = *reinterpret_cast<const float4*>(&sw[4]);
    const float w0 = wa.x, w1 = wa.y, w2 = wa.z, w3 = wa.w,
                w4 = wb.x, w5 = wb.y, w6 = wb.z;

    // Chunk 0: outputs [p0 .. p0+3]. Middle float4 == v0 (register reuse).
    {
        const float4 a = *reinterpret_cast<const float4*>(&s[p0]);
        const float4 b = v0;
        const float4 c = *reinterpret_cast<const float4*>(&s[p0 + 8]);
        float4 r;
        r.x = w0*a.y + w1*a.z + w2*a.w + w3*b.x + w4*b.y + w5*b.z + w6*b.w;
        r.y = w0*a.z + w1*a.w + w2*b.x + w3*b.y + w4*b.z + w5*b.w + w6*c.x;
        r.z = w0*a.w + w1*b.x + w2*b.y + w3*b.z + w4*b.w + w5*c.x + w6*c.y;
        r.w = w0*b.x + w1*b.y + w2*b.z + w3*b.w + w4*c.x + w5*c.y + w6*c.z;
        __stcs(reinterpret_cast<float4*>(out + base + p0), r);
    }

    // Chunk 1: outputs [p1 .. p1+3]. Middle float4 == v1.
    {
        const float4 a = *reinterpret_cast<const float4*>(&s[p1]);
        const float4 b = v1;
        const float4 c = *reinterpret_cast<const float4*>(&s[p1 + 8]);
        float4 r;
        r.x = w0*a.y + w1*a.z + w2*a.w + w3*b.x + w4*b.y + w5*b.z + w6*b.w;
        r.y = w0*a.z + w1*a.w + w2*b.x + w3*b.y + w4*b.z + w5*b.w + w6*c.x;
        r.z = w0*a.w + w1*b.x + w2*b.y + w3*b.z + w4*b.w + w5*c.x + w6*c.y;
        r.w = w0*b.x + w1*b.y + w2*b.z + w3*b.w + w4*c.x + w5*c.y + w6*c.z;
        __stcs(reinterpret_cast<float4*>(out + base + p1), r);
    }
}

extern "C" void kernel_launch(void* const* d_in, const int* in_sizes, int n_in,
                              void* d_out, int out_size) {
    const float* x = (const float*)d_in[0];
    const float* w = (const float*)d_in[1];
    float* out = (float*)d_out;

    const int rows = in_sizes[0] / T_LEN;   // B*C = 16384

    dim3 grid(T_LEN / TILE, rows);          // (2, 16384)
    lconv1d_fused_kernel<<<grid, THREADS>>>(x, w, out);
}